// round 10
// baseline (speedup 1.0000x reference)
#include <cuda_runtime.h>
#include <math.h>

#define NCTA 128
#define NTHR 512

// smem (float4 units):
//   wG   [0, 12336)        : 48 gatecols x 257 (GRU weights, resident)
//   xb   [12336, 14384)    : 2 x 1024 chunk buffers (GRU: e 512 + d 512)
//     ph3 overlay: per buf [0..512) x-chunk, [512..584) w-chunk (8x9)
//     ph1 overlay: scratch 64x25 = 1600 f4; wSa 8x25 = 200 f4 at +1600
#define WG_F4   12336
#define SMEM_F4 (WG_F4 + 2048)
#define SMEM_BYTES (SMEM_F4 * 16)   // 230144 <= 232448

typedef unsigned long long u64;
typedef ulonglong2 ull2;

__device__ __forceinline__ u64 fma2(u64 a, u64 b, u64 c) {
    u64 d;
    asm("fma.rn.f32x2 %0, %1, %2, %3;" : "=l"(d) : "l"(a), "l"(b), "l"(c));
    return d;
}
__device__ __forceinline__ float hsum(u64 v) {
    union { u64 u; float f[2]; } x; x.u = v;
    return x.f[0] + x.f[1];
}
__device__ __forceinline__ float sigm(float x) { return 1.f / (1.f + expf(-x)); }
__device__ __forceinline__ float softplusf(float x) {
    return fmaxf(x, 0.f) + log1pf(expf(-fabsf(x)));
}
__device__ __forceinline__ void cpa16(float4* dst, const void* src) {
    unsigned s = (unsigned)__cvta_generic_to_shared(dst);
    asm volatile("cp.async.cg.shared.global [%0], [%1], 16;" :: "r"(s), "l"(src));
}
#define CP_COMMIT() asm volatile("cp.async.commit_group;" ::: "memory")
#define CP_WAIT1()  asm volatile("cp.async.wait_group 1;" ::: "memory")
#define CP_WAIT0()  asm volatile("cp.async.wait_group 0;" ::: "memory")

// ---------------- persistent state ----------------
__device__ float g_emb[64 * 1024];
__device__ float g_det[2][64 * 1024];
__device__ float g_h1[64 * 512];
__device__ float g_hq[64 * 512];
__device__ float g_stoch[64 * 32];
__device__ float g_obsq[64 * 256 * 512];
__device__ unsigned g_cnt;
__device__ volatile unsigned g_gen;

// grid barrier: fence only in thread0 (cumulative), 128 co-resident CTAs
__device__ __forceinline__ void gbar() {
    __syncthreads();
    if (threadIdx.x == 0) {
        __threadfence();
        unsigned gen = g_gen;
        if (atomicAdd(&g_cnt, 1u) == NCTA - 1) {
            g_cnt = 0;
            __threadfence();
            g_gen = gen + 1;
        } else {
            while (g_gen == gen) { }
        }
        __threadfence();
    }
    __syncthreads();
}

// ======== pre-pass: g_obsq[r][c] = obs[r]·Wq1[c][1024:] + bq1[c] ========
__global__ void __launch_bounds__(256)
obsq_kernel(const float* __restrict__ obs, const float* __restrict__ Wq1,
            const float* __restrict__ bq1) {
    extern __shared__ float4 S[];
    const int tid = threadIdx.x, lane = tid & 31, wrp = tid >> 5;
    const int rt = blockIdx.x >> 2, ct = blockIdx.x & 3;
    const int r0 = rt * 64, c0 = ct * 128;
    const int rh = wrp >> 2, cgq = wrp & 3;

    u64 acc[32];
    #pragma unroll
    for (int j = 0; j < 32; ++j) acc[j] = 0ull;

    for (int c = 0; c < 16; ++c) {
        for (int i = tid; i < 1024; i += 256) {
            int row = i >> 4, k4 = i & 15;
            S[row * 17 + k4] = *(const float4*)(obs + (size_t)(r0 + row) * 1024 + c * 64 + k4 * 4);
        }
        for (int i = tid; i < 2048; i += 256) {
            int col = i >> 4, k4 = i & 15;
            S[1088 + col * 16 + k4] =
                *(const float4*)(Wq1 + (size_t)(c0 + col) * 2048 + 1024 + c * 64 + k4 * 4);
        }
        __syncthreads();
        const ull2* xr = (const ull2*)(S + (rh * 32 + lane) * 17);
        const ull2* wb = (const ull2*)(S + 1088 + (cgq * 32) * 16);
        for (int k4 = 0; k4 < 16; ++k4) {
            ull2 x = xr[k4];
            #pragma unroll
            for (int j = 0; j < 32; ++j) {
                ull2 w = wb[j * 16 + k4];
                acc[j] = fma2(w.x, x.x, acc[j]);
                acc[j] = fma2(w.y, x.y, acc[j]);
            }
        }
        __syncthreads();
    }
    int r = r0 + rh * 32 + lane;
    #pragma unroll
    for (int j = 0; j < 32; ++j) {
        int col = c0 + cgq * 32 + j;
        g_obsq[(size_t)r * 512 + col] = hsum(acc[j]) + bq1[col];
    }
}

// ======== persistent rollout ========
__global__ void __launch_bounds__(NTHR, 1)
rssm_kernel(const float* __restrict__ obs,   const float* __restrict__ act,
            const float* __restrict__ nzp,   const float* __restrict__ nzq,
            const float* __restrict__ Wsa, const float* __restrict__ bsa,
            const float* __restrict__ Wih, const float* __restrict__ bih,
            const float* __restrict__ Whh, const float* __restrict__ bhh,
            const float* __restrict__ Wp1, const float* __restrict__ bp1,
            const float* __restrict__ Wp2, const float* __restrict__ bp2,
            const float* __restrict__ Wq1, const float* __restrict__ bq1,
            const float* __restrict__ Wq2, const float* __restrict__ bq2,
            float* __restrict__ out)
{
    extern __shared__ float4 S[];
    float4* wG = S;
    float4* xb = S + WG_F4;

    const int tid  = threadIdx.x;
    const int lane = tid & 31;
    const int wrp  = tid >> 5;
    const int c0g  = blockIdx.x * 8;

    // GRU tiling ids: warp = 16 rows x 2 cols; thread = 2 rows x 3 gates (one matrix)
    const int gw_r = wrp & 3;             // row group (16 rows)
    const int gw_c = wrp >> 2;            // col group (2 cols)
    const int tr   = lane & 7;
    const int tc   = lane >> 3;           // 0..3
    const int gr0  = gw_r * 16 + tr;      // row 0
    const int gr1  = gr0 + 8;             // row 1
    const int gcol = gw_c * 2 + (tc >> 1);           // 0..7 within CTA
    const int gpar = (tc & 1);                        // 0 = i-gates (emb), 1 = h-gates (det)
    // ph3/ph1 tiling: warp = 8 rows x 4 cols; thread = 1 output
    const int pr   = (wrp & 7) * 8 + (lane & 7);      // row 0..63
    const int pc   = (wrp >> 3) * 4 + (lane >> 3);    // col 0..7

    // ---- init: zero state, load GRU weights into smem [gc][257] ----
    for (int i = blockIdx.x * NTHR + tid; i < 64 * 1024; i += NCTA * NTHR)
        g_det[0][i] = 0.f;
    for (int i = blockIdx.x * NTHR + tid; i < 64 * 32; i += NCTA * NTHR)
        g_stoch[i] = 0.f;
    for (int i = tid; i < WG_F4; i += NTHR) {
        int gc = i / 257, k = i - gc * 257;
        if (k < 256) {
            int col = gc / 6, g = gc - col * 6;
            const float* srow = (g < 3)
                ? (Wih + ((size_t)(c0g + col) + 1024 * g) * 1024)
                : (Whh + ((size_t)(c0g + col) + 1024 * (g - 3)) * 1024);
            wG[i] = *(const float4*)(srow + k * 4);
        }
    }
    gbar();

    // GRU per-thread weight bases: 3 gates at gc = gcol*6 + gpar*3 + {0,1,2}
    const float4* wg0 = wG + (gcol * 6 + gpar * 3 + 0) * 257;
    const float4* wg1 = wG + (gcol * 6 + gpar * 3 + 1) * 257;
    const float4* wg2 = wG + (gcol * 6 + gpar * 3 + 2) * 257;

    for (int t = 0; t < 256; ++t) {
        const int p = t & 1;
        const float* detP = g_det[p];
        float*       detN = g_det[p ^ 1];

        // ===== phase 1: emb = relu([stoch|act] @ Wsa^T + bsa) =====
        {
            float4* scr = xb;            // 64 x 25
            float4* wsa = xb + 1600;     // 8 x 25
            for (int i = tid; i < 1536; i += NTHR) {
                int row = i / 24, k4 = i - row * 24;
                const void* src = (k4 < 8)
                    ? (const void*)(g_stoch + row * 32 + k4 * 4)
                    : (const void*)(act + ((size_t)row * 256 + t) * 64 + (k4 - 8) * 4);
                cpa16(scr + row * 25 + k4, src);
            }
            if (tid < 192) {
                int c = tid / 24, k4 = tid - c * 24;
                cpa16(wsa + c * 25 + k4, Wsa + (size_t)(c0g + c) * 96 + k4 * 4);
            }
            CP_COMMIT(); CP_WAIT0();
            __syncthreads();
            u64 a = 0;
            #pragma unroll 6
            for (int k4 = 0; k4 < 24; ++k4) {
                ull2 x = *(const ull2*)(scr + pr * 25 + k4);
                ull2 w = *(const ull2*)(wsa + pc * 25 + k4);
                a = fma2(w.x, x.x, a); a = fma2(w.y, x.y, a);
            }
            g_emb[(size_t)pr * 1024 + c0g + pc] = fmaxf(hsum(a) + bsa[c0g + pc], 0.f);
        }
        gbar();

        // ===== phase 2: GRU =====
        {
            float4* b0 = xb;
            float4* b1 = xb + 1024;
            u64 acc[6] = {0, 0, 0, 0, 0, 0};   // [r01*3 + gate]

            auto stageG = [&](float4* buf, int j) {
                #pragma unroll
                for (int s = 0; s < 2; ++s) {
                    int i = tid + s * 512;
                    int mat = i >> 9, idx = i & 511, row = idx >> 3, k4 = idx & 7;
                    const float* src = (mat ? detP : g_emb)
                        + (size_t)row * 1024 + j * 32 + k4 * 4;
                    cpa16(buf + mat * 512 + row * 8 + (k4 ^ (row & 7)), src);
                }
            };
            stageG(b0, 0); CP_COMMIT();
            stageG(b1, 1); CP_COMMIT();

            const int xbase0 = gpar * 512 + gr0 * 8;
            const int xbase1 = gpar * 512 + gr1 * 8;
            for (int j = 0; j < 32; ++j) {
                if (j == 31) CP_WAIT0(); else CP_WAIT1();
                __syncthreads();
                const float4* buf = (j & 1) ? b1 : b0;
                const float4* w0 = wg0 + j * 8;
                const float4* w1 = wg1 + j * 8;
                const float4* w2 = wg2 + j * 8;
                #pragma unroll
                for (int k4 = 0; k4 < 8; ++k4) {
                    int sk = k4 ^ tr;
                    ull2 x0 = *(const ull2*)(buf + xbase0 + sk);
                    ull2 x1 = *(const ull2*)(buf + xbase1 + sk);
                    ull2 wa = *(const ull2*)(w0 + k4);
                    ull2 wb = *(const ull2*)(w1 + k4);
                    ull2 wc = *(const ull2*)(w2 + k4);
                    acc[0] = fma2(wa.x, x0.x, acc[0]); acc[0] = fma2(wa.y, x0.y, acc[0]);
                    acc[1] = fma2(wb.x, x0.x, acc[1]); acc[1] = fma2(wb.y, x0.y, acc[1]);
                    acc[2] = fma2(wc.x, x0.x, acc[2]); acc[2] = fma2(wc.y, x0.y, acc[2]);
                    acc[3] = fma2(wa.x, x1.x, acc[3]); acc[3] = fma2(wa.y, x1.y, acc[3]);
                    acc[4] = fma2(wb.x, x1.x, acc[4]); acc[4] = fma2(wb.y, x1.y, acc[4]);
                    acc[5] = fma2(wc.x, x1.x, acc[5]); acc[5] = fma2(wc.y, x1.y, acc[5]);
                }
                __syncthreads();
                if (j < 30) { stageG((j & 1) ? b1 : b0, j + 2); CP_COMMIT(); }
            }

            const int col = c0g + gcol;
            const float* bb = gpar ? bhh : bih;
            float s[6];
            #pragma unroll
            for (int r01 = 0; r01 < 2; ++r01)
                #pragma unroll
                for (int m = 0; m < 3; ++m)
                    s[r01 * 3 + m] = hsum(acc[r01 * 3 + m]) + bb[col + 1024 * m];
            float o[6];
            #pragma unroll
            for (int i = 0; i < 6; ++i)
                o[i] = __shfl_xor_sync(0xffffffffu, s[i], 8);
            if (!gpar) {
                #pragma unroll
                for (int r01 = 0; r01 < 2; ++r01) {
                    int row = r01 ? gr1 : gr0;
                    float r  = sigm(s[r01 * 3 + 0] + o[r01 * 3 + 0]);
                    float z  = sigm(s[r01 * 3 + 1] + o[r01 * 3 + 1]);
                    float n  = tanhf(s[r01 * 3 + 2] + r * o[r01 * 3 + 2]);
                    float hp = detP[(size_t)row * 1024 + col];
                    float hw = (1.f - z) * n + z * hp;
                    detN[(size_t)row * 1024 + col] = hw;
                    out[((size_t)row * 256 + t) * 1216 + col] = hw;
                }
            }
        }
        gbar();

        // ===== phase 3: h1 / hq first layers (K=1024 both; obs part precomputed) =====
        {
            const bool isQ = blockIdx.x & 1;
            const int  c0  = (blockIdx.x >> 1) * 8;
            const float* W1 = isQ ? Wq1 : Wp1;
            const size_t K1 = isQ ? 2048 : 1024;
            float4* b0 = xb;
            float4* b1 = xb + 1024;
            u64 a = 0;

            auto stage3 = [&](float4* buf, int j) {
                {
                    int row = tid >> 3, k4 = tid & 7;
                    if (tid < 512)
                        cpa16(buf + row * 8 + (k4 ^ (row & 7)),
                              detN + (size_t)row * 1024 + j * 32 + k4 * 4);
                }
                if (tid < 64) {
                    int c = tid >> 3, k4 = tid & 7;
                    cpa16(buf + 512 + c * 9 + k4,
                          W1 + (size_t)(c0 + c) * K1 + j * 32 + k4 * 4);
                }
            };
            stage3(b0, 0); CP_COMMIT();
            stage3(b1, 1); CP_COMMIT();

            for (int j = 0; j < 32; ++j) {
                if (j == 31) CP_WAIT0(); else CP_WAIT1();
                __syncthreads();
                const float4* buf = (j & 1) ? b1 : b0;
                #pragma unroll
                for (int k4 = 0; k4 < 8; ++k4) {
                    ull2 x = *(const ull2*)(buf + pr * 8 + (k4 ^ (pr & 7)));
                    ull2 w = *(const ull2*)(buf + 512 + pc * 9 + k4);
                    a = fma2(w.x, x.x, a); a = fma2(w.y, x.y, a);
                }
                __syncthreads();
                if (j < 30) { stage3((j & 1) ? b1 : b0, j + 2); CP_COMMIT(); }
            }

            const int col = c0 + pc;
            float base = isQ ? g_obsq[((size_t)pr * 256 + t) * 512 + col] : bp1[col];
            float v = fmaxf(hsum(a) + base, 0.f);
            (isQ ? g_hq : g_h1)[(size_t)pr * 512 + col] = v;
        }
        gbar();

        // ===== phase 4: second-layer heads, stochastic state =====
        {
            const int gw = blockIdx.x * 16 + wrp;       // 0..2047
            #pragma unroll
            for (int i = 0; i < 2; ++i) {
                int pi    = gw * 2 + i;                 // 0..4095
                int which = pi & 1;
                int s     = (pi >> 1) & 31;
                int bb    = pi >> 6;
                const float* h  = (which ? g_hq : g_h1) + (size_t)bb * 512;
                const float* W2 = which ? Wq2 : Wp2;
                u64 am = 0, asd = 0;
                #pragma unroll
                for (int q = 0; q < 4; ++q) {
                    float4 xf = __ldcg((const float4*)(h + lane * 16 + q * 4));
                    ull2 x = *(ull2*)&xf;
                    ull2 u = *(const ull2*)(W2 + (size_t)s * 512 + lane * 16 + q * 4);
                    ull2 v = *(const ull2*)(W2 + (size_t)(s + 32) * 512 + lane * 16 + q * 4);
                    am  = fma2(u.x, x.x, am);  am  = fma2(u.y, x.y, am);
                    asd = fma2(v.x, x.x, asd); asd = fma2(v.y, x.y, asd);
                }
                float sm = hsum(am), ss = hsum(asd);
                #pragma unroll
                for (int o = 16; o; o >>= 1) {
                    sm += __shfl_xor_sync(0xffffffffu, sm, o);
                    ss += __shfl_xor_sync(0xffffffffu, ss, o);
                }
                if (lane == 0) {
                    const float* b2 = which ? bq2 : bp2;
                    float mean = sm + b2[s];
                    float stdv = softplusf(ss + b2[s + 32]) + 1e-5f;
                    const float* nz = which ? nzq : nzp;
                    float e  = nz[((size_t)bb * 256 + t) * 32 + s];
                    float st = mean + stdv * e;
                    size_t base = ((size_t)bb * 256 + t) * 1216 + 1024 + which * 96;
                    out[base + s]      = mean;
                    out[base + 32 + s] = stdv;
                    out[base + 64 + s] = st;
                    if (which) g_stoch[bb * 32 + s] = st;
                }
            }
        }
        gbar();
    }
}

extern "C" void kernel_launch(void* const* d_in, const int* in_sizes, int n_in,
                              void* d_out, int out_size) {
    (void)in_sizes; (void)n_in; (void)out_size;
    cudaFuncSetAttribute((const void*)obsq_kernel,
                         cudaFuncAttributeMaxDynamicSharedMemorySize, 50176);
    cudaFuncSetAttribute((const void*)rssm_kernel,
                         cudaFuncAttributeMaxDynamicSharedMemorySize, SMEM_BYTES);
    obsq_kernel<<<1024, 256, 50176>>>(
        (const float*)d_in[0], (const float*)d_in[14], (const float*)d_in[15]);
    rssm_kernel<<<NCTA, NTHR, SMEM_BYTES>>>(
        (const float*)d_in[0],  (const float*)d_in[1],
        (const float*)d_in[2],  (const float*)d_in[3],
        (const float*)d_in[4],  (const float*)d_in[5],
        (const float*)d_in[6],  (const float*)d_in[7],
        (const float*)d_in[8],  (const float*)d_in[9],
        (const float*)d_in[10], (const float*)d_in[11],
        (const float*)d_in[12], (const float*)d_in[13],
        (const float*)d_in[14], (const float*)d_in[15],
        (const float*)d_in[16], (const float*)d_in[17],
        (float*)d_out);
}